// round 11
// baseline (speedup 1.0000x reference)
#include <cuda_runtime.h>
#include <cuda_fp16.h>
#include <mma.h>
#include <cstdint>

using namespace nvcuda;

// Problem constants (fixed by the dataset)
#define Bc 4
#define Qc 4096
#define Cc 256
#define Mh 8
#define Lc 4
#define Pc 4
#define Dc 32
#define Nc 21760
#define BQ (Bc*Qc)          // 16384

// Scratch (device globals; allocation-free rule)
__device__ __half g_vph[(size_t)Bc*Mh*Nc*Dc]; // [B,M,N,D] head-major vproj, fp16
__device__ __half g_headsh[(size_t)BQ*256];   // sampled heads, half
__device__ float  g_qout[(size_t)BQ*384];     // fused [logits(128) | offsets(256)]
__device__ __half g_wqh[256*384];             // concat weights half
__device__ __half g_wvh[256*256];             // W_val half
__device__ __half g_woh[256*256];             // W_out half
__device__ float  g_bq[384];                  // concat bias

__device__ __forceinline__ uint32_t pack_h2(float a, float b) {
    __half2 t = __floats2half2_rn(a, b);
    return *reinterpret_cast<uint32_t*>(&t);
}
__device__ __forceinline__ void cp_async16(void* sdst, const void* gsrc) {
    uint32_t s = (uint32_t)__cvta_generic_to_shared(sdst);
    asm volatile("cp.async.cg.shared.global [%0], [%1], 16;" :: "r"(s), "l"(gsrc));
}
__device__ __forceinline__ void cp_commit() {
    asm volatile("cp.async.commit_group;");
}
template<int N>
__device__ __forceinline__ void cp_wait() {
    asm volatile("cp.async.wait_group %0;" :: "n"(N));
}

// ---------------------------------------------------------------------------
// Weight prep: concat W_attn|W_off -> g_wqh (half), convert W_val/W_out,
// concat biases. <<<256, 384>>>
// ---------------------------------------------------------------------------
__global__ void prep_weights(const float* __restrict__ Wa, const float* __restrict__ Wo,
                             const float* __restrict__ ba, const float* __restrict__ bo,
                             const float* __restrict__ Wv, const float* __restrict__ Wu) {
    const int r = blockIdx.x;
    const int c = threadIdx.x;
    g_wqh[r * 384 + c] = __float2half((c < 128) ? Wa[r * 128 + c] : Wo[r * 256 + (c - 128)]);
    if (c < 256) {
        g_wvh[r * 256 + c] = __float2half(Wv[r * 256 + c]);
        g_woh[r * 256 + c] = __float2half(Wu[r * 256 + c]);
    }
    if (r == 0) g_bq[c] = (c < 128) ? ba[c] : bo[c - 128];
}

// ---------------------------------------------------------------------------
// fp16 tensor-core GEMM, cp.async double-buffered, fused A conversion.
// C[Md,Nd] = A[Md,256] @ B[256,Nd] + bias[Nd];  B half in GMEM.
// A_FP32 1: A fp32 in GMEM (staged fp32 smem -> half smem). 0: A half.
// BM=128, BN=64, BK=64. 256 thr = 8 warps (4x2); warp 32x32, m16n16k16.
// rowOfs: global row offset of this launch's row block (for batch splits).
// STORE_MODE 0: fp32 row-major direct frag stores.
// STORE_MODE 1: fp16 permuted store -> g_vph[B,M,N,D] (staged via smem).
// ---------------------------------------------------------------------------
template<int A_FP32, int STORE_MODE>
__global__ __launch_bounds__(256, 2)
void gemm_h(const void* __restrict__ Ain, const __half* __restrict__ Bm,
            const float* __restrict__ bias, float* __restrict__ Cd, int Nd,
            int rowOfs) {
    constexpr int BM = 128, BN = 64, BK = 64;
    constexpr int AKp = 72;                 // half A smem pitch (halves), 144B
    constexpr int A32p = 68;                // fp32 A stage pitch (floats), 272B
    constexpr int BNp = 72;                 // B smem pitch (halves)
    constexpr int ASZH = BM * AKp;          // 9216 halves
    constexpr int A32SZ = BM * A32p;        // 8704 floats / stage
    constexpr int BSZH = BK * BNp;          // 4608 halves / stage

    extern __shared__ __align__(16) char smem[];
    float*  A32[2];
    __half* Ahalf[2];
    __half* Bs[2];
    float*  biasS;
    if (A_FP32) {
        A32[0]   = (float*)smem;
        A32[1]   = (float*)smem + A32SZ;
        Ahalf[0] = (__half*)(smem + 2 * A32SZ * 4);
        Ahalf[1] = Ahalf[0];
        Bs[0]    = Ahalf[0] + ASZH;
        Bs[1]    = Bs[0] + BSZH;
        biasS    = (float*)(Bs[1] + BSZH);
    } else {
        Ahalf[0] = (__half*)smem;
        Ahalf[1] = Ahalf[0] + ASZH;
        Bs[0]    = Ahalf[1] + ASZH;
        Bs[1]    = Bs[0] + BSZH;
        biasS    = (float*)(Bs[1] + BSZH);
    }

    const int tid = threadIdx.x;
    const int wid = tid >> 5;
    const int warpRow = (wid >> 1) * 32;   // 0,32,64,96
    const int warpCol = (wid & 1) * 32;    // 0,32
    const int rowBase = blockIdx.y * BM + rowOfs;
    const int colBase = blockIdx.x * BN;

    const float*  Af = (const float*)Ain;
    const __half* Ah = (const __half*)Ain;

    auto issue = [&](int st, int k0) {
        if (A_FP32) {
            #pragma unroll
            for (int i = 0; i < 8; i++) {
                int idx = tid + i * 256;
                int r = idx >> 4, c4 = (idx & 15) * 4;
                cp_async16(&A32[st][r * A32p + c4],
                           Af + (size_t)(rowBase + r) * Cc + k0 + c4);
            }
        } else {
            #pragma unroll
            for (int i = 0; i < 4; i++) {
                int idx = tid + i * 256;
                int r = idx >> 3, c8 = (idx & 7) * 8;
                cp_async16(&Ahalf[st][r * AKp + c8],
                           Ah + (size_t)(rowBase + r) * Cc + k0 + c8);
            }
        }
        #pragma unroll
        for (int i = 0; i < 2; i++) {
            int idx = tid + i * 256;
            int r = idx >> 3, c8 = (idx & 7) * 8;
            cp_async16(&Bs[st][r * BNp + c8],
                       Bm + (size_t)(k0 + r) * Nd + colBase + c8);
        }
    };

    issue(0, 0);
    cp_commit();

    #pragma unroll
    for (int i = tid; i < 16 * BN; i += 256) {
        int r = i >> 6, c = i & 63;
        biasS[r * BNp + c] = bias[colBase + c];
    }
    __syncthreads();

    wmma::fragment<wmma::accumulator, 16, 16, 16, float> acc[2][2];
    #pragma unroll
    for (int i = 0; i < 2; i++)
        #pragma unroll
        for (int j = 0; j < 2; j++)
            wmma::load_matrix_sync(acc[i][j], &biasS[warpCol + j * 16], BNp,
                                   wmma::mem_row_major);

    #pragma unroll
    for (int t = 0; t < 4; t++) {
        if (t < 3) { issue((t + 1) & 1, (t + 1) * BK); cp_commit(); cp_wait<1>(); }
        else cp_wait<0>();
        __syncthreads();

        if (A_FP32) {
            const float* src = A32[t & 1];
            #pragma unroll
            for (int i = 0; i < 8; i++) {
                int idx = tid + i * 256;
                int r = idx >> 4, c4 = (idx & 15) * 4;
                float4 vv = *(const float4*)&src[r * A32p + c4];
                *(uint2*)&Ahalf[0][r * AKp + c4] =
                    make_uint2(pack_h2(vv.x, vv.y), pack_h2(vv.z, vv.w));
            }
            __syncthreads();
        }

        const __half* Ab = Ahalf[A_FP32 ? 0 : (t & 1)];
        const __half* Bb = Bs[t & 1];
        #pragma unroll
        for (int kk = 0; kk < BK; kk += 16) {
            wmma::fragment<wmma::matrix_a, 16, 16, 16, __half, wmma::row_major> af[2];
            wmma::fragment<wmma::matrix_b, 16, 16, 16, __half, wmma::row_major> bf[2];
            #pragma unroll
            for (int i = 0; i < 2; i++)
                wmma::load_matrix_sync(af[i], &Ab[(warpRow + i * 16) * AKp + kk], AKp);
            #pragma unroll
            for (int j = 0; j < 2; j++)
                wmma::load_matrix_sync(bf[j], &Bb[kk * BNp + warpCol + j * 16], BNp);
            #pragma unroll
            for (int i = 0; i < 2; i++)
                #pragma unroll
                for (int j = 0; j < 2; j++)
                    wmma::mma_sync(acc[i][j], af[i], bf[j], acc[i][j]);
        }
        __syncthreads();
    }

    if (STORE_MODE == 0) {
        #pragma unroll
        for (int i = 0; i < 2; i++) {
            int row0 = rowBase + warpRow + i * 16;
            #pragma unroll
            for (int j = 0; j < 2; j++) {
                int col0 = colBase + warpCol + j * 16;
                wmma::store_matrix_sync(Cd + (size_t)row0 * Nd + col0, acc[i][j],
                                        Nd, wmma::mem_row_major);
            }
        }
    } else {
        constexpr int SP = 68;
        float* stage = (float*)smem;
        __syncthreads();
        #pragma unroll
        for (int i = 0; i < 2; i++)
            #pragma unroll
            for (int j = 0; j < 2; j++)
                wmma::store_matrix_sync(&stage[(warpRow + i * 16) * SP + warpCol + j * 16],
                                        acc[i][j], SP, wmma::mem_row_major);
        __syncthreads();
        #pragma unroll
        for (int i = 0; i < 8; i++) {
            int idx = tid + i * 256;
            int r = idx >> 4, c4 = (idx & 15) * 4;
            float4 v = *(const float4*)&stage[r * SP + c4];
            int row0 = rowBase + r;
            int colG = colBase + c4;
            int b = row0 / Nc, n = row0 - b * Nc;
            int m = colG >> 5, d = colG & 31;
            __half* ptr = g_vph + (((size_t)((b * Mh + m) * Nc) + n) << 5) + d;
            *(uint2*)ptr = make_uint2(pack_h2(v.x, v.y), pack_h2(v.z, v.w));
        }
    }
}

// ---------------------------------------------------------------------------
// Warp-autonomous sampling for ONE batch: one warp per (q,head).
// ---------------------------------------------------------------------------
__global__ void sample_kernel(const float* __restrict__ p,
                              const int* __restrict__ shapes,
                              const int* __restrict__ level_index,
                              int bIdx) {
    const unsigned FULL = 0xffffffffu;
    const int w = (blockIdx.x * blockDim.x + threadIdx.x) >> 5;
    const int lane = threadIdx.x & 31;
    const int bq = bIdx * Qc + (w >> 3);
    const int m = w & 7;
    const int b = bIdx;

    const float offv = g_qout[bq * 384 + 128 + m * 32 + lane];

    float lg = (lane < 16) ? g_qout[bq * 384 + m * 16 + lane] : -1e30f;
    float mx = lg;
    #pragma unroll
    for (int s = 8; s; s >>= 1) mx = fmaxf(mx, __shfl_xor_sync(FULL, mx, s));
    float e = (lane < 16) ? __expf(lg - mx) : 0.f;
    float sum = e;
    #pragma unroll
    for (int s = 8; s; s >>= 1) sum += __shfl_xor_sync(FULL, sum, s);
    const float awv = e / sum;

    const int pt  = lane >> 1;
    const int grp = lane & 1;
    const int l = pt >> 2;
    const int H  = shapes[2*l + 0];
    const int Wd = shapes[2*l + 1];
    const float px = p[bq * 8 + 2*l + 0];
    const float py = p[bq * 8 + 2*l + 1];
    const int base = level_index[l];

    const float ox = __shfl_sync(FULL, offv, pt * 2);
    const float oy = __shfl_sync(FULL, offv, pt * 2 + 1);
    const float aw = __shfl_sync(FULL, awv, pt);

    const float x = fmaf(px, (float)Wd, ox) - 0.5f;
    const float y = fmaf(py, (float)H,  oy) - 0.5f;
    const float x0f = floorf(x), y0f = floorf(y);
    const float lx = x - x0f, ly = y - y0f;
    const int x0 = (int)x0f, y0 = (int)y0f;

    const bool inx0 = (unsigned)x0       < (unsigned)Wd;
    const bool inx1 = (unsigned)(x0 + 1) < (unsigned)Wd;
    const bool iny0 = (unsigned)y0       < (unsigned)H;
    const bool iny1 = (unsigned)(y0 + 1) < (unsigned)H;

    float w11 = aw * lx * ly;
    float w10 = aw * lx - w11;
    float w01 = aw * ly - w11;
    float w00 = aw - w10 - w01 - w11;
    w00 = (inx0 & iny0) ? w00 : 0.f;
    w10 = (inx1 & iny0) ? w10 : 0.f;
    w01 = (inx0 & iny1) ? w01 : 0.f;
    w11 = (inx1 & iny1) ? w11 : 0.f;

    const int x0c = min(max(x0, 0), Wd - 1);
    const int x1c = min(max(x0 + 1, 0), Wd - 1);
    const int y0c = min(max(y0, 0), H - 1);
    const int y1c = min(max(y0 + 1, 0), H - 1);
    const int i00 = base + y0c * Wd + x0c;
    const int dx  = x1c - x0c;
    const int dyW = (y1c - y0c) * Wd;

    const float wtop = grp ? w10 : w00;
    const float wbot = grp ? w11 : w01;
    const int   itop = i00 + dx * grp;
    const int   ibot = itop + dyW;

    const int myg = lane >> 4;
    const __half* __restrict__ vpb =
        g_vph + ((size_t)((b * Mh + m) * Nc) << 5) + (lane & 15) * 2;

    float accx = 0.f, accy = 0.f;
    #pragma unroll
    for (int qq = 0; qq < 16; qq++) {
        const int src = qq * 2 + myg;
        const float wt = __shfl_sync(FULL, wtop, src);
        const float wb = __shfl_sync(FULL, wbot, src);
        const int it = __shfl_sync(FULL, itop, src);
        const int ib = __shfl_sync(FULL, ibot, src);
        const float2 tv = __half22float2(*(const __half2*)(vpb + (it << 5)));
        const float2 bv = __half22float2(*(const __half2*)(vpb + (ib << 5)));
        accx = fmaf(wt, tv.x, fmaf(wb, bv.x, accx));
        accy = fmaf(wt, tv.y, fmaf(wb, bv.y, accy));
    }
    accx += __shfl_xor_sync(FULL, accx, 16);
    accy += __shfl_xor_sync(FULL, accy, 16);

    if (lane < 16)
        *(__half2*)(g_headsh + bq * 256 + m * 32 + lane * 2) =
            __floats2half2_rn(accx, accy);
}

// ---------------------------------------------------------------------------
extern "C" void kernel_launch(void* const* d_in, const int* in_sizes, int n_in,
                              void* d_out, int out_size) {
    const float* q       = (const float*)d_in[0];
    const float* p       = (const float*)d_in[1];
    const float* v       = (const float*)d_in[2];
    const int*   shapes  = (const int*)d_in[3];
    const int*   lvl_idx = (const int*)d_in[4];
    const float* W_off   = (const float*)d_in[5];
    const float* b_off   = (const float*)d_in[6];
    const float* W_attn  = (const float*)d_in[7];
    const float* b_attn  = (const float*)d_in[8];
    const float* W_val   = (const float*)d_in[9];
    const float* b_val   = (const float*)d_in[10];
    const float* W_out   = (const float*)d_in[11];
    const float* b_out   = (const float*)d_in[12];
    float* out = (float*)d_out;

    __half* headsh;cudaGetSymbolAddress((void**)&headsh,g_headsh);
    float*  qout;  cudaGetSymbolAddress((void**)&qout,  g_qout);
    __half* wqh;   cudaGetSymbolAddress((void**)&wqh,   g_wqh);
    __half* wvh;   cudaGetSymbolAddress((void**)&wvh,   g_wvh);
    __half* woh;   cudaGetSymbolAddress((void**)&woh,   g_woh);
    float*  bqv;   cudaGetSymbolAddress((void**)&bqv,   g_bq);

    const int smem32 = 2 * 128 * 68 * 4 + 128 * 72 * 2 + 2 * 64 * 72 * 2 + 16 * 72 * 4;
    const int smemH  = 2 * (128 * 72 * 2 + 64 * 72 * 2) + 16 * 72 * 4;

    static cudaStream_t s2 = nullptr;
    static cudaEvent_t evPrep = nullptr, evV[Bc], evS[Bc];
    if (!s2) {
        cudaStreamCreateWithFlags(&s2, cudaStreamNonBlocking);
        cudaEventCreateWithFlags(&evPrep, cudaEventDisableTiming);
        for (int b = 0; b < Bc; b++) {
            cudaEventCreateWithFlags(&evV[b], cudaEventDisableTiming);
            cudaEventCreateWithFlags(&evS[b], cudaEventDisableTiming);
        }
        cudaFuncSetAttribute(gemm_h<1, 1>, cudaFuncAttributeMaxDynamicSharedMemorySize, smem32);
        cudaFuncSetAttribute(gemm_h<1, 0>, cudaFuncAttributeMaxDynamicSharedMemorySize, smem32);
        cudaFuncSetAttribute(gemm_h<0, 0>, cudaFuncAttributeMaxDynamicSharedMemorySize, smemH);
    }

    // 0) weight prep (feeds both branches)
    prep_weights<<<256, 384>>>(W_attn, W_off, b_attn, b_off, W_val, W_out);
    cudaEventRecord(evPrep, 0);
    cudaStreamWaitEvent(s2, evPrep, 0);

    // 1) fused logits+offsets on s2 (concurrent with vproj batches)
    {
        dim3 grid(384 / 64, BQ / 128);          // (6, 128)
        gemm_h<1, 0><<<grid, 256, smem32, s2>>>(q, wqh, bqv, qout, 384, 0);
    }

    // 2) value projection, batch-split on main stream
    for (int b = 0; b < Bc; b++) {
        dim3 grid(Cc / 64, Nc / 128);           // (4, 170)
        gemm_h<1, 1><<<grid, 256, smem32>>>(v, wvh, b_val, nullptr, Cc, b * Nc);
        cudaEventRecord(evV[b], 0);
    }

    // 3) sampling per batch on s2 (after qout in stream order; waits vproj(b))
    for (int b = 0; b < Bc; b++) {
        cudaStreamWaitEvent(s2, evV[b], 0);
        sample_kernel<<<(Qc * Mh) / 8, 256, 0, s2>>>(p, shapes, lvl_idx, b);
        cudaEventRecord(evS[b], s2);
    }

    // 4) output projection per batch on main stream (joins s2 work)
    for (int b = 0; b < Bc; b++) {
        cudaStreamWaitEvent(0, evS[b], 0);
        dim3 grid(Cc / 64, Qc / 128);           // (4, 32)
        gemm_h<0, 0><<<grid, 256, smemH>>>(headsh + (size_t)b * Qc * 256, woh,
                                           b_out, out + (size_t)b * Qc * 256, Cc, 0);
    }
}

// round 12
// speedup vs baseline: 1.1139x; 1.1139x over previous
#include <cuda_runtime.h>
#include <cuda_fp16.h>
#include <mma.h>
#include <cstdint>

using namespace nvcuda;

// Problem constants (fixed by the dataset)
#define Bc 4
#define Qc 4096
#define Cc 256
#define Mh 8
#define Lc 4
#define Pc 4
#define Dc 32
#define Nc 21760
#define BQ (Bc*Qc)          // 16384

// Scratch (device globals; allocation-free rule)
__device__ __half g_vph[(size_t)Bc*Mh*Nc*Dc]; // [B,M,N,D] head-major vproj, fp16
__device__ __half g_vh[(size_t)Bc*Nc*Cc];     // v in half
__device__ __half g_qh[(size_t)BQ*Cc];        // q in half
__device__ __half g_headsh[(size_t)BQ*256];   // sampled heads, half
__device__ float  g_qout[(size_t)BQ*384];     // fused [logits(128) | offsets(256)]
__device__ __half g_wqh[256*384];             // concat weights half
__device__ __half g_wvh[256*256];             // W_val half
__device__ __half g_woh[256*256];             // W_out half
__device__ float  g_bq[384];                  // concat bias

__device__ __forceinline__ uint32_t pack_h2(float a, float b) {
    __half2 t = __floats2half2_rn(a, b);
    return *reinterpret_cast<uint32_t*>(&t);
}
__device__ __forceinline__ void cp_async16(void* sdst, const void* gsrc) {
    uint32_t s = (uint32_t)__cvta_generic_to_shared(sdst);
    asm volatile("cp.async.cg.shared.global [%0], [%1], 16;" :: "r"(s), "l"(gsrc));
}
__device__ __forceinline__ void cp_commit() {
    asm volatile("cp.async.commit_group;");
}
template<int N>
__device__ __forceinline__ void cp_wait() {
    asm volatile("cp.async.wait_group %0;" :: "n"(N));
}

// ---------------------------------------------------------------------------
// Streaming fp32 -> fp16 conversion (vectorized). n4 = n/4.
// ---------------------------------------------------------------------------
__global__ void cvt_f2h(const float4* __restrict__ src, __half* __restrict__ dst,
                        int n4) {
    int i = blockIdx.x * blockDim.x + threadIdx.x;
    if (i < n4) {
        float4 v = src[i];
        *(uint2*)(dst + (size_t)i * 4) = make_uint2(pack_h2(v.x, v.y), pack_h2(v.z, v.w));
    }
}

// ---------------------------------------------------------------------------
// Weight prep: concat W_attn|W_off -> g_wqh (half), convert W_val/W_out,
// concat biases. <<<256, 384>>>
// ---------------------------------------------------------------------------
__global__ void prep_weights(const float* __restrict__ Wa, const float* __restrict__ Wo,
                             const float* __restrict__ ba, const float* __restrict__ bo,
                             const float* __restrict__ Wv, const float* __restrict__ Wu) {
    const int r = blockIdx.x;
    const int c = threadIdx.x;
    g_wqh[r * 384 + c] = __float2half((c < 128) ? Wa[r * 128 + c] : Wo[r * 256 + (c - 128)]);
    if (c < 256) {
        g_wvh[r * 256 + c] = __float2half(Wv[r * 256 + c]);
        g_woh[r * 256 + c] = __float2half(Wu[r * 256 + c]);
    }
    if (r == 0) g_bq[c] = (c < 128) ? ba[c] : bo[c - 128];
}

// ---------------------------------------------------------------------------
// fp16 tensor-core GEMM, cp.async double-buffered, 2 CTAs/SM (R8 config).
// C[Md,Nd] = A[Md,256] @ B[256,Nd] + bias[Nd];  A,B half in GMEM.
// BM=128, BN=64, BK=64. 256 threads = 8 warps (4 row x 2 col); warp 32x32
// via 2x2 wmma m16n16k16, fp32 accumulate. Bias preloaded into accumulators.
// STORE_MODE 0: fp32 row-major direct frag stores.
// STORE_MODE 1: fp16 permuted store -> g_vph[B,M,N,D] (staged via smem).
// ---------------------------------------------------------------------------
template<int STORE_MODE>
__global__ __launch_bounds__(256, 2)
void gemm_h(const __half* __restrict__ A, const __half* __restrict__ Bm,
            const float* __restrict__ bias, float* __restrict__ Cd, int Nd) {
    constexpr int BM = 128, BN = 64, BK = 64;
    constexpr int AKp = 72;                 // A smem pitch (halves), 144B
    constexpr int BNp = 72;                 // B smem pitch (halves)
    constexpr int ASZH = BM * AKp;          // 9216 halves / stage
    constexpr int BSZH = BK * BNp;          // 4608 halves / stage

    extern __shared__ __align__(16) char smem[];
    __half* As[2] = { (__half*)smem, (__half*)smem + ASZH };
    __half* Bs[2] = { (__half*)smem + 2 * ASZH, (__half*)smem + 2 * ASZH + BSZH };
    float* biasS = (float*)(smem + (2 * ASZH + 2 * BSZH) * 2);  // 16 x BNp floats

    const int tid = threadIdx.x;
    const int wid = tid >> 5;
    const int warpRow = (wid >> 1) * 32;   // 0,32,64,96
    const int warpCol = (wid & 1) * 32;    // 0,32
    const int rowBase = blockIdx.y * BM;
    const int colBase = blockIdx.x * BN;

    auto issue = [&](int st, int k0) {
        #pragma unroll
        for (int i = 0; i < 4; i++) {
            int idx = tid + i * 256;
            int r = idx >> 3, c8 = (idx & 7) * 8;
            cp_async16(&As[st][r * AKp + c8],
                       A + (size_t)(rowBase + r) * Cc + k0 + c8);
        }
        #pragma unroll
        for (int i = 0; i < 2; i++) {
            int idx = tid + i * 256;
            int r = idx >> 3, c8 = (idx & 7) * 8;
            cp_async16(&Bs[st][r * BNp + c8],
                       Bm + (size_t)(k0 + r) * Nd + colBase + c8);
        }
    };

    issue(0, 0);
    cp_commit();

    #pragma unroll
    for (int i = tid; i < 16 * BN; i += 256) {
        int r = i >> 6, c = i & 63;
        biasS[r * BNp + c] = bias[colBase + c];
    }
    __syncthreads();

    wmma::fragment<wmma::accumulator, 16, 16, 16, float> acc[2][2];
    #pragma unroll
    for (int i = 0; i < 2; i++)
        #pragma unroll
        for (int j = 0; j < 2; j++)
            wmma::load_matrix_sync(acc[i][j], &biasS[warpCol + j * 16], BNp,
                                   wmma::mem_row_major);

    #pragma unroll
    for (int t = 0; t < 4; t++) {
        if (t < 3) { issue((t + 1) & 1, (t + 1) * BK); cp_commit(); cp_wait<1>(); }
        else cp_wait<0>();
        __syncthreads();

        const __half* Ab = As[t & 1];
        const __half* Bb = Bs[t & 1];
        #pragma unroll
        for (int kk = 0; kk < BK; kk += 16) {
            wmma::fragment<wmma::matrix_a, 16, 16, 16, __half, wmma::row_major> af[2];
            wmma::fragment<wmma::matrix_b, 16, 16, 16, __half, wmma::row_major> bf[2];
            #pragma unroll
            for (int i = 0; i < 2; i++)
                wmma::load_matrix_sync(af[i], &Ab[(warpRow + i * 16) * AKp + kk], AKp);
            #pragma unroll
            for (int j = 0; j < 2; j++)
                wmma::load_matrix_sync(bf[j], &Bb[kk * BNp + warpCol + j * 16], BNp);
            #pragma unroll
            for (int i = 0; i < 2; i++)
                #pragma unroll
                for (int j = 0; j < 2; j++)
                    wmma::mma_sync(acc[i][j], af[i], bf[j], acc[i][j]);
        }
        __syncthreads();
    }

    if (STORE_MODE == 0) {
        #pragma unroll
        for (int i = 0; i < 2; i++) {
            int row0 = rowBase + warpRow + i * 16;
            #pragma unroll
            for (int j = 0; j < 2; j++) {
                int col0 = colBase + warpCol + j * 16;
                wmma::store_matrix_sync(Cd + (size_t)row0 * Nd + col0, acc[i][j],
                                        Nd, wmma::mem_row_major);
            }
        }
    } else {
        // ---- staged fp16 permuted store -> g_vph ----
        constexpr int SP = 68;
        float* stage = (float*)smem;           // 128*68*4 = 34816 B (fits)
        __syncthreads();
        #pragma unroll
        for (int i = 0; i < 2; i++)
            #pragma unroll
            for (int j = 0; j < 2; j++)
                wmma::store_matrix_sync(&stage[(warpRow + i * 16) * SP + warpCol + j * 16],
                                        acc[i][j], SP, wmma::mem_row_major);
        __syncthreads();
        #pragma unroll
        for (int i = 0; i < 8; i++) {
            int idx = tid + i * 256;
            int r = idx >> 4, c4 = (idx & 15) * 4;
            float4 v = *(const float4*)&stage[r * SP + c4];
            int row0 = rowBase + r;
            int colG = colBase + c4;
            int b = row0 / Nc, n = row0 - b * Nc;
            int m = colG >> 5, d = colG & 31;
            __half* ptr = g_vph + (((size_t)((b * Mh + m) * Nc) + n) << 5) + d;
            *(uint2*)ptr = make_uint2(pack_h2(v.x, v.y), pack_h2(v.z, v.w));
        }
    }
}

// ---------------------------------------------------------------------------
// Warp-autonomous sampling: one warp per (b,q,head). Paired-corner __half2
// gathers. Per-point params are gathered into register arrays first (packed
// 16+16-bit index pairs — all indices < Nc < 2^15) so the consumer loop can
// issue loads with high MLP.
// ---------------------------------------------------------------------------
__global__ void sample_kernel(const float* __restrict__ p,
                              const int* __restrict__ shapes,
                              const int* __restrict__ level_index) {
    const unsigned FULL = 0xffffffffu;
    const int w = (blockIdx.x * blockDim.x + threadIdx.x) >> 5;
    const int lane = threadIdx.x & 31;
    const int bq = w >> 3;
    const int m = w & 7;
    const int b = bq >> 12;

    const float offv = g_qout[bq * 384 + 128 + m * 32 + lane];

    float lg = (lane < 16) ? g_qout[bq * 384 + m * 16 + lane] : -1e30f;
    float mx = lg;
    #pragma unroll
    for (int s = 8; s; s >>= 1) mx = fmaxf(mx, __shfl_xor_sync(FULL, mx, s));
    float e = (lane < 16) ? __expf(lg - mx) : 0.f;
    float sum = e;
    #pragma unroll
    for (int s = 8; s; s >>= 1) sum += __shfl_xor_sync(FULL, sum, s);
    const float awv = e / sum;

    // per-(point, corner-group) precompute: lane = pt*2 + grp
    const int pt  = lane >> 1;
    const int grp = lane & 1;
    const int l = pt >> 2;
    const int H  = shapes[2*l + 0];
    const int Wd = shapes[2*l + 1];
    const float px = p[bq * 8 + 2*l + 0];
    const float py = p[bq * 8 + 2*l + 1];
    const int base = level_index[l];

    const float ox = __shfl_sync(FULL, offv, pt * 2);
    const float oy = __shfl_sync(FULL, offv, pt * 2 + 1);
    const float aw = __shfl_sync(FULL, awv, pt);

    const float x = fmaf(px, (float)Wd, ox) - 0.5f;
    const float y = fmaf(py, (float)H,  oy) - 0.5f;
    const float x0f = floorf(x), y0f = floorf(y);
    const float lx = x - x0f, ly = y - y0f;
    const int x0 = (int)x0f, y0 = (int)y0f;

    const bool inx0 = (unsigned)x0       < (unsigned)Wd;
    const bool inx1 = (unsigned)(x0 + 1) < (unsigned)Wd;
    const bool iny0 = (unsigned)y0       < (unsigned)H;
    const bool iny1 = (unsigned)(y0 + 1) < (unsigned)H;

    float w11 = aw * lx * ly;
    float w10 = aw * lx - w11;
    float w01 = aw * ly - w11;
    float w00 = aw - w10 - w01 - w11;
    w00 = (inx0 & iny0) ? w00 : 0.f;
    w10 = (inx1 & iny0) ? w10 : 0.f;
    w01 = (inx0 & iny1) ? w01 : 0.f;
    w11 = (inx1 & iny1) ? w11 : 0.f;

    const int x0c = min(max(x0, 0), Wd - 1);
    const int x1c = min(max(x0 + 1, 0), Wd - 1);
    const int y0c = min(max(y0, 0), H - 1);
    const int y1c = min(max(y0 + 1, 0), H - 1);
    const int i00 = base + y0c * Wd + x0c;
    const int dx  = x1c - x0c;
    const int dyW = (y1c - y0c) * Wd;

    const float wtop = grp ? w10 : w00;
    const float wbot = grp ? w11 : w01;
    const int   itop = i00 + dx * grp;
    const int   ibot = itop + dyW;
    const int   ipack = itop | (ibot << 16);   // both < 2^15

    // ---- gather all per-point params into registers (high-MLP consumer) ----
    const int myg = lane >> 4;
    int   pki[16];
    float wts[16], wbs[16];
    #pragma unroll
    for (int qq = 0; qq < 16; qq++) {
        const int src = qq * 2 + myg;
        pki[qq] = __shfl_sync(FULL, ipack, src);
        wts[qq] = __shfl_sync(FULL, wtop, src);
        wbs[qq] = __shfl_sync(FULL, wbot, src);
    }

    const __half* __restrict__ vpb =
        g_vph + ((size_t)((b * Mh + m) * Nc) << 5) + (lane & 15) * 2;

    float accx = 0.f, accy = 0.f;
    #pragma unroll
    for (int qq = 0; qq < 16; qq++) {
        const int it = pki[qq] & 0xFFFF;
        const int ib = pki[qq] >> 16;
        const float2 tv = __half22float2(*(const __half2*)(vpb + (it << 5)));
        const float2 bv = __half22float2(*(const __half2*)(vpb + (ib << 5)));
        accx = fmaf(wts[qq], tv.x, fmaf(wbs[qq], bv.x, accx));
        accy = fmaf(wts[qq], tv.y, fmaf(wbs[qq], bv.y, accy));
    }
    accx += __shfl_xor_sync(FULL, accx, 16);
    accy += __shfl_xor_sync(FULL, accy, 16);

    if (lane < 16)
        *(__half2*)(g_headsh + bq * 256 + m * 32 + lane * 2) =
            __floats2half2_rn(accx, accy);
}

// ---------------------------------------------------------------------------
extern "C" void kernel_launch(void* const* d_in, const int* in_sizes, int n_in,
                              void* d_out, int out_size) {
    const float* q       = (const float*)d_in[0];
    const float* p       = (const float*)d_in[1];
    const float* v       = (const float*)d_in[2];
    const int*   shapes  = (const int*)d_in[3];
    const int*   lvl_idx = (const int*)d_in[4];
    const float* W_off   = (const float*)d_in[5];
    const float* b_off   = (const float*)d_in[6];
    const float* W_attn  = (const float*)d_in[7];
    const float* b_attn  = (const float*)d_in[8];
    const float* W_val   = (const float*)d_in[9];
    const float* b_val   = (const float*)d_in[10];
    const float* W_out   = (const float*)d_in[11];
    const float* b_out   = (const float*)d_in[12];
    float* out = (float*)d_out;

    __half* vh;    cudaGetSymbolAddress((void**)&vh,    g_vh);
    __half* qh;    cudaGetSymbolAddress((void**)&qh,    g_qh);
    __half* headsh;cudaGetSymbolAddress((void**)&headsh,g_headsh);
    float*  qout;  cudaGetSymbolAddress((void**)&qout,  g_qout);
    __half* wqh;   cudaGetSymbolAddress((void**)&wqh,   g_wqh);
    __half* wvh;   cudaGetSymbolAddress((void**)&wvh,   g_wvh);
    __half* woh;   cudaGetSymbolAddress((void**)&woh,   g_woh);
    float*  bqv;   cudaGetSymbolAddress((void**)&bqv,   g_bq);

    // smem: 2 stages * (A 18432B + B 9216B) + bias 16*72*4 = 59904 B
    const int smemH = 2 * (128 * 72 * 2 + 64 * 72 * 2) + 16 * 72 * 4;

    static cudaStream_t s2 = nullptr;
    static cudaEvent_t evPrep = nullptr, evQ = nullptr;
    if (!s2) {
        cudaStreamCreateWithFlags(&s2, cudaStreamNonBlocking);
        cudaEventCreateWithFlags(&evPrep, cudaEventDisableTiming);
        cudaEventCreateWithFlags(&evQ, cudaEventDisableTiming);
        cudaFuncSetAttribute(gemm_h<0>, cudaFuncAttributeMaxDynamicSharedMemorySize, smemH);
        cudaFuncSetAttribute(gemm_h<1>, cudaFuncAttributeMaxDynamicSharedMemorySize, smemH);
    }

    // 0) weight prep (feeds both streams)
    prep_weights<<<256, 384>>>(W_attn, W_off, b_attn, b_off, W_val, W_out);
    cudaEventRecord(evPrep, 0);
    cudaStreamWaitEvent(s2, evPrep, 0);

    // s2: cvt_q -> qout GEMM (tensor-bound; overlaps DRAM-bound cvt_v on main)
    cvt_f2h<<<(BQ * Cc / 4 + 255) / 256, 256, 0, s2>>>((const float4*)q, qh, BQ * Cc / 4);
    {
        dim3 grid(384 / 64, BQ / 128);          // (6, 128)
        gemm_h<0><<<grid, 256, smemH, s2>>>(qh, wqh, bqv, qout, 384);
    }
    cudaEventRecord(evQ, s2);

    // main: cvt_v (DRAM-bound) -> vproj
    cvt_f2h<<<(Bc * Nc * Cc / 4 + 255) / 256, 256>>>((const float4*)v, vh, Bc * Nc * Cc / 4);
    {
        dim3 grid(Cc / 64, (Bc * Nc) / 128);    // (4, 680)
        gemm_h<1><<<grid, 256, smemH>>>(vh, wvh, b_val, nullptr, Cc);
    }

    // join, then sample + out on main
    cudaStreamWaitEvent(0, evQ, 0);
    sample_kernel<<<(BQ * Mh) / 8, 256>>>(p, shapes, lvl_idx);
    {
        dim3 grid(Cc / 64, BQ / 128);           // (4, 128)
        gemm_h<0><<<grid, 256, smemH>>>(headsh, woh, b_out, out, Cc);
    }
}